// round 1
// baseline (speedup 1.0000x reference)
#include <cuda_runtime.h>
#include <cuda_bf16.h>

#define SEQ   512
#define T_LEN 65536
#define NN    131072
#define NHALF 65536
#define N1    128
#define N2    1024
#define TILE  32
#define L2N1  7
#define L2N2  10

// Scratch (device globals; no allocations allowed)
__device__ float2 g_z[(size_t)SEQ * NN];   // 512 MiB workspace
__device__ float2 g_tw[NN];                // twiddles: g_tw[h+p] = exp(-i*pi*p/h)

static __device__ __forceinline__ float2 cmul(float2 a, float2 b) {
    return make_float2(fmaf(a.x, b.x, -a.y * b.y), fmaf(a.x, b.y, a.y * b.x));
}
// a * conj(b)
static __device__ __forceinline__ float2 cmulc(float2 a, float2 b) {
    return make_float2(fmaf(a.x, b.x, a.y * b.y), fmaf(a.y, b.x, -a.x * b.y));
}

__global__ void k_init_tw() {
    int idx = blockIdx.x * blockDim.x + threadIdx.x;
    if (idx >= NN) return;
    if (idx == 0) { g_tw[0] = make_float2(1.0f, 0.0f); return; }
    int h = 1 << (31 - __clz(idx));
    int p = idx - h;
    double ang = -3.14159265358979323846 * (double)p / (double)h;
    double s, c;
    sincos(ang, &s, &c);
    g_tw[idx] = make_float2((float)c, (float)s);
}

// ---------------------------------------------------------------------------
// Pass A: fused pack (bf16-quantize x, z = x + i*h, zero-pad) + forward
// FFT-128 along the strided (n1) dimension + inter-step twiddle W_N^{k1*n2}.
// DIF: natural-order load, bit-reversed row positions at the end (harmless:
// each row segment is stored as a contiguous 256B chunk; row order arbitrary).
// Output layout: g_z[s][k1*N2 + n2] = G[k1][n2].
// ---------------------------------------------------------------------------
__global__ void __launch_bounds__(256) k_stage1(const float* __restrict__ x,
                                                const float* __restrict__ hk) {
    __shared__ float2 sm[N1 * TILE];
    const int s = blockIdx.y;
    const int n2base = blockIdx.x * TILE;
    const int tid = threadIdx.x;
    const float* xs = x + (size_t)s * T_LEN;
    const float* hs = hk + (size_t)s * T_LEN;

    for (int i = tid; i < N1 * TILE; i += 256) {
        int row = i >> 5, col = i & 31;
        int n = row * N2 + n2base + col;
        float2 v = make_float2(0.0f, 0.0f);
        if (n < T_LEN) {
            v.x = __bfloat162float(__float2bfloat16_rn(xs[n]));
            v.y = hs[n];
        }
        sm[i] = v;
    }
    __syncthreads();

    // forward DIF over the row (n1) dimension, 32 columns in parallel
    for (int sh = L2N1 - 1; sh >= 0; sh--) {
        int half = 1 << sh;
        for (int w = tid; w < (N1 / 2) * TILE; w += 256) {
            int col = w & 31;
            int b = w >> 5;
            int pos = b & (half - 1);
            int base = ((b >> sh) << (sh + 1)) + pos;
            float2 tw = g_tw[half + pos];
            int ia = base * TILE + col;
            int ja = ia + half * TILE;
            float2 u = sm[ia], v = sm[ja];
            sm[ia] = make_float2(u.x + v.x, u.y + v.y);
            float2 d = make_float2(u.x - v.x, u.y - v.y);
            sm[ja] = cmul(d, tw);
        }
        __syncthreads();
    }

    // inter-step twiddle + store (smem row p holds k1 = bitrev7(p))
    float2* zs = g_z + (size_t)s * NN;
    for (int i = tid; i < N1 * TILE; i += 256) {
        int prow = i >> 5, col = i & 31;
        int k1 = __brev((unsigned)prow) >> (32 - L2N1);
        int n2 = n2base + col;
        int idx = k1 * n2;                       // < 2*NHALF
        float sgn = 1.0f;
        if (idx >= NHALF) { idx -= NHALF; sgn = -1.0f; }
        float2 w = g_tw[NHALF + idx];            // W_N^{idx}
        float2 v = cmul(sm[i], w);
        zs[k1 * N2 + n2] = make_float2(sgn * v.x, sgn * v.y);
    }
}

// ---------------------------------------------------------------------------
// Pass BCD (fused): rows {g, 128-g} (block 0 handles {0, 64}):
//   forward DIF-1024 (spectrum lands in bit-reversed positions)
//   -> Hermitian unpack of X,H from Z + pointwise multiply, done directly in
//      bit-reversed positions (pair (p, 1023-p) since brev(~k)=~brev(k))
//   -> inverse DIT-1024 (bitrev in -> natural out)
//   -> conj inter-step twiddle W_N^{-k1*m2}, store in place.
// ---------------------------------------------------------------------------
__global__ void __launch_bounds__(256) k_stage2() {
    __shared__ float2 smA[N2];
    __shared__ float2 smB[N2];
    const int s = blockIdx.y;
    const int g = blockIdx.x;                    // 0..63
    const int rowA = g;
    const int rowB = (g == 0) ? (N1 / 2) : (N1 - g);
    const int tid = threadIdx.x;
    float2* zs = g_z + (size_t)s * NN;
    float2* pA = zs + rowA * N2;
    float2* pB = zs + rowB * N2;

    for (int j = tid; j < N2; j += 256) { smA[j] = pA[j]; smB[j] = pB[j]; }
    __syncthreads();

    // forward DIF, both rows
    for (int sh = L2N2 - 1; sh >= 0; sh--) {
        int half = 1 << sh;
        for (int w = tid; w < N2; w += 256) {
            float2* sm = (w < (N2 / 2)) ? smA : smB;
            int b = w & (N2 / 2 - 1);
            int pos = b & (half - 1);
            int base = ((b >> sh) << (sh + 1)) + pos;
            float2 tw = g_tw[half + pos];
            float2 u = sm[base], v = sm[base + half];
            sm[base] = make_float2(u.x + v.x, u.y + v.y);
            float2 d = make_float2(u.x - v.x, u.y - v.y);
            sm[base + half] = cmul(d, tw);
        }
        __syncthreads();
    }

    // pointwise: X=(Z(k)+conj(Z(N-k)))/2, H=-i(Z(k)-conj(Z(N-k)))/2, Y=XH
    if (g != 0) {
        for (int p = tid; p < N2; p += 256) {
            float2 Za = smA[p];
            float2 Zb = smB[(N2 - 1) - p];
            float2 X = make_float2(0.5f * (Za.x + Zb.x), 0.5f * (Za.y - Zb.y));
            float2 H = make_float2(0.5f * (Za.y + Zb.y), -0.5f * (Za.x - Zb.x));
            float2 Y = cmul(X, H);
            smA[p] = Y;
            smB[(N2 - 1) - p] = make_float2(Y.x, -Y.y);
        }
    } else {
        // row 0: k2 pairs with (N2 - k2) mod N2; resolve via explicit bitrev
        for (int k2 = tid; k2 <= N2 / 2; k2 += 256) {
            int pa = __brev((unsigned)k2) >> (32 - L2N2);
            int pb = __brev((unsigned)((N2 - k2) & (N2 - 1))) >> (32 - L2N2);
            float2 Za = smA[pa];
            float2 Zb = smA[pb];
            float2 X = make_float2(0.5f * (Za.x + Zb.x), 0.5f * (Za.y - Zb.y));
            float2 H = make_float2(0.5f * (Za.y + Zb.y), -0.5f * (Za.x - Zb.x));
            float2 Y = cmul(X, H);
            smA[pa] = Y;
            smA[pb] = make_float2(Y.x, -Y.y);
        }
        // row 64: self-paired, clean (p, 1023-p) pairing
        for (int p = tid; p < N2 / 2; p += 256) {
            float2 Za = smB[p];
            float2 Zb = smB[(N2 - 1) - p];
            float2 X = make_float2(0.5f * (Za.x + Zb.x), 0.5f * (Za.y - Zb.y));
            float2 H = make_float2(0.5f * (Za.y + Zb.y), -0.5f * (Za.x - Zb.x));
            float2 Y = cmul(X, H);
            smB[p] = Y;
            smB[(N2 - 1) - p] = make_float2(Y.x, -Y.y);
        }
    }
    __syncthreads();

    // inverse DIT, both rows (bitrev in -> natural out), unscaled
    for (int sh = 0; sh < L2N2; sh++) {
        int half = 1 << sh;
        for (int w = tid; w < N2; w += 256) {
            float2* sm = (w < (N2 / 2)) ? smA : smB;
            int b = w & (N2 / 2 - 1);
            int pos = b & (half - 1);
            int base = ((b >> sh) << (sh + 1)) + pos;
            float2 tw = g_tw[half + pos];
            float2 u = sm[base];
            float2 v = cmulc(sm[base + half], tw);
            sm[base] = make_float2(u.x + v.x, u.y + v.y);
            sm[base + half] = make_float2(u.x - v.x, u.y - v.y);
        }
        __syncthreads();
    }

    // conj inter-step twiddle + store
    for (int j = tid; j < N2; j += 256) {
        {
            int idx = rowA * j;
            float sgn = 1.0f;
            if (idx >= NHALF) { idx -= NHALF; sgn = -1.0f; }
            float2 w = g_tw[NHALF + idx];
            float2 v = cmulc(smA[j], w);
            pA[j] = make_float2(sgn * v.x, sgn * v.y);
        }
        {
            int idx = rowB * j;
            float sgn = 1.0f;
            if (idx >= NHALF) { idx -= NHALF; sgn = -1.0f; }
            float2 w = g_tw[NHALF + idx];
            float2 v = cmulc(smB[j], w);
            pB[j] = make_float2(sgn * v.x, sgn * v.y);
        }
    }
}

// ---------------------------------------------------------------------------
// Pass E: inverse FFT-128 along the strided (k1) dimension, 1/N scale,
// write real part of samples n < T only (causal truncation).
// DIT: load rows into bit-reversed smem positions, output natural m1 order.
// ---------------------------------------------------------------------------
__global__ void __launch_bounds__(256) k_stage3(float* __restrict__ out) {
    __shared__ float2 sm[N1 * TILE];
    const int s = blockIdx.y;
    const int n2base = blockIdx.x * TILE;
    const int tid = threadIdx.x;
    float2* zs = g_z + (size_t)s * NN;

    for (int i = tid; i < N1 * TILE; i += 256) {
        int k1 = i >> 5, col = i & 31;
        int rb = __brev((unsigned)k1) >> (32 - L2N1);
        sm[rb * TILE + col] = zs[k1 * N2 + n2base + col];
    }
    __syncthreads();

    for (int sh = 0; sh < L2N1; sh++) {
        int half = 1 << sh;
        for (int w = tid; w < (N1 / 2) * TILE; w += 256) {
            int col = w & 31;
            int b = w >> 5;
            int pos = b & (half - 1);
            int base = ((b >> sh) << (sh + 1)) + pos;
            float2 tw = g_tw[half + pos];
            int ia = base * TILE + col;
            int ja = ia + half * TILE;
            float2 u = sm[ia];
            float2 v = cmulc(sm[ja], tw);
            sm[ia] = make_float2(u.x + v.x, u.y + v.y);
            sm[ja] = make_float2(u.x - v.x, u.y - v.y);
        }
        __syncthreads();
    }

    const float scale = 1.0f / (float)NN;
    float* os = out + (size_t)s * T_LEN;
    for (int i = tid; i < (N1 / 2) * TILE; i += 256) {
        int m1 = i >> 5, col = i & 31;
        os[m1 * N2 + n2base + col] = sm[m1 * TILE + col].x * scale;
    }
}

extern "C" void kernel_launch(void* const* d_in, const int* in_sizes, int n_in,
                              void* d_out, int out_size) {
    const float* x = (const float*)d_in[0];
    const float* h = (const float*)d_in[1];
    float* out = (float*)d_out;

    k_init_tw<<<NN / 256, 256>>>();

    dim3 gA(N2 / TILE, SEQ);
    k_stage1<<<gA, 256>>>(x, h);

    dim3 gB(N1 / 2, SEQ);
    k_stage2<<<gB, 256>>>();

    dim3 gC(N2 / TILE, SEQ);
    k_stage3<<<gC, 256>>>(out);
}

// round 2
// speedup vs baseline: 3.0501x; 3.0501x over previous
#include <cuda_runtime.h>
#include <cuda_bf16.h>

#define SEQ   512
#define T_LEN 65536
#define NN    131072
#define NHALF 65536
#define N2    2048

// Scratch (device globals; no allocations allowed)
__device__ float2 g_z[(size_t)SEQ * NN];   // 512 MiB workspace
__device__ float2 g_tw[NN];                // g_tw[h+p] = exp(-i*pi*p/h)

static __device__ __forceinline__ float2 cmul(float2 a, float2 b) {
    return make_float2(fmaf(a.x, b.x, -a.y * b.y), fmaf(a.x, b.y, a.y * b.x));
}
static __device__ __forceinline__ float2 cadd(float2 a, float2 b) { return make_float2(a.x+b.x, a.y+b.y); }
static __device__ __forceinline__ float2 csub(float2 a, float2 b) { return make_float2(a.x-b.x, a.y-b.y); }
static __device__ __forceinline__ float2 mulnI(float2 a) { return make_float2(a.y, -a.x); }   // * (-i)
static __device__ __forceinline__ float2 mulpI(float2 a) { return make_float2(-a.y, a.x); }   // * (+i)
static __device__ __forceinline__ float2 cconj(float2 a) { return make_float2(a.x, -a.y); }

// W_{2*Mhalf}^q  for q in [0, 2*Mhalf)
static __device__ __forceinline__ float2 twid(int Mhalf, int q) {
    if (q < Mhalf) return g_tw[Mhalf + q];
    float2 t = g_tw[q];                    // == g_tw[Mhalf + (q - Mhalf)]
    return make_float2(-t.x, -t.y);
}

// 8-pt DFT, natural in/out. INV => conjugated twiddles (unnormalized inverse).
template<bool INV>
static __device__ __forceinline__ void fft8(float2 z[8]) {
    const float C = 0.70710678118654752440f;
    float2 t0=cadd(z[0],z[4]), t1=cadd(z[1],z[5]), t2=cadd(z[2],z[6]), t3=cadd(z[3],z[7]);
    float2 s0=csub(z[0],z[4]), s1=csub(z[1],z[5]), s2=csub(z[2],z[6]), s3=csub(z[3],z[7]);
    if (!INV) {
        s1 = cmul(s1, make_float2(C,-C)); s2 = mulnI(s2); s3 = cmul(s3, make_float2(-C,-C));
    } else {
        s1 = cmul(s1, make_float2(C, C)); s2 = mulpI(s2); s3 = cmul(s3, make_float2(-C, C));
    }
    float2 a0=cadd(t0,t2), a1=csub(t0,t2), a2=cadd(t1,t3), a3=csub(t1,t3);
    a3 = INV ? mulpI(a3) : mulnI(a3);
    float2 b0=cadd(s0,s2), b1=csub(s0,s2), b2=cadd(s1,s3), b3=csub(s1,s3);
    b3 = INV ? mulpI(b3) : mulnI(b3);
    z[0]=cadd(a0,a2); z[4]=csub(a0,a2);
    z[2]=cadd(a1,a3); z[6]=csub(a1,a3);
    z[1]=cadd(b0,b2); z[5]=csub(b0,b2);
    z[3]=cadd(b1,b3); z[7]=csub(b1,b3);
}

template<bool INV>
static __device__ __forceinline__ void fft4(float2 z[4]) {
    float2 a0=cadd(z[0],z[2]), a1=csub(z[0],z[2]);
    float2 a2=cadd(z[1],z[3]), a3=csub(z[1],z[3]);
    a3 = INV ? mulpI(a3) : mulnI(a3);
    z[0]=cadd(a0,a2); z[2]=csub(a0,a2);
    z[1]=cadd(a1,a3); z[3]=csub(a1,a3);
}

// Hermitian unpack + pointwise: Za = Z[k], Zb = Z[N-k]; returns Y[k] = X[k]*H[k]
static __device__ __forceinline__ float2 pw(float2 Za, float2 Zb) {
    float2 X = make_float2(0.5f*(Za.x+Zb.x),  0.5f*(Za.y-Zb.y));
    float2 H = make_float2(0.5f*(Za.y+Zb.y), -0.5f*(Za.x-Zb.x));
    return cmul(X, H);
}

#define PAD(p) ((p) + (((p) >> 5) << 2))
#define POS(k2) ((((k2)&7)<<8) + ((((k2)>>3)&7)<<5) + ((((k2)>>6)&7)<<2) + ((k2)>>9))

__global__ void k_init_tw() {
    int idx = blockIdx.x * blockDim.x + threadIdx.x;
    if (idx >= NN) return;
    if (idx == 0) { g_tw[0] = make_float2(1.0f, 0.0f); return; }
    int h = 1 << (31 - __clz(idx));
    int p = idx - h;
    double ang = -3.14159265358979323846 * (double)p / (double)h;
    double s, c;
    sincos(ang, &s, &c);
    g_tw[idx] = make_float2((float)c, (float)s);
}

// ---------------------------------------------------------------------------
// Stage 1: pack z = bf16(x) + i*h (rows n1>=32 are zero) + 64-pt FFT along n1
// (two register radix-8 passes, one smem exchange) + twiddle W_N^{k1*n2}.
// Output: g_z[s][k1*2048 + n2]
// ---------------------------------------------------------------------------
__global__ void __launch_bounds__(256) k_stage1(const float* __restrict__ x,
                                                const float* __restrict__ hk) {
    __shared__ float2 sm[64 * 32];
    const int s   = blockIdx.y;
    const int col = threadIdx.x & 31;
    const int a   = threadIdx.x >> 5;          // 0..7
    const int n2  = blockIdx.x * 32 + col;
    const float* xs = x  + (size_t)s * T_LEN;
    const float* hs = hk + (size_t)s * T_LEN;

    float2 v[8];
    #pragma unroll
    for (int b = 0; b < 4; b++) {
        int n = (a + 8*b) * N2 + n2;           // < 65536 always
        v[b] = make_float2(__bfloat162float(__float2bfloat16_rn(xs[n])), hs[n]);
    }
    // fft8 over b with upper half zero (t = z, s = z)
    {
        const float C = 0.70710678118654752440f;
        float2 t0=v[0], t1=v[1], t2=v[2], t3=v[3];
        float2 s0=v[0];
        float2 s1=cmul(v[1], make_float2(C,-C));
        float2 s2=mulnI(v[2]);
        float2 s3=cmul(v[3], make_float2(-C,-C));
        float2 a0=cadd(t0,t2), a1=csub(t0,t2), a2=cadd(t1,t3), a3=mulnI(csub(t1,t3));
        float2 b0=cadd(s0,s2), b1=csub(s0,s2), b2=cadd(s1,s3), b3=mulnI(csub(s1,s3));
        v[0]=cadd(a0,a2); v[4]=csub(a0,a2);
        v[2]=cadd(a1,a3); v[6]=csub(a1,a3);
        v[1]=cadd(b0,b2); v[5]=csub(b0,b2);
        v[3]=cadd(b1,b3); v[7]=csub(b1,b3);
    }
    // twiddle W_64^{a*j}
    {
        float2 w = twid(32, a), acc = w;
        #pragma unroll
        for (int j = 1; j < 8; j++) { v[j] = cmul(v[j], acc); acc = cmul(acc, w); }
    }
    #pragma unroll
    for (int j = 0; j < 8; j++) sm[(j*8 + a)*32 + col] = v[j];
    __syncthreads();

    const int j = a;                            // phase-2 role
    #pragma unroll
    for (int q = 0; q < 8; q++) v[q] = sm[(j*8 + q)*32 + col];
    fft8<false>(v);                             // over a -> m ; k1 = j + 8m

    float2* zs = g_z + (size_t)s * NN;
    {
        float2 acc  = twid(NHALF, n2 * j);      // n2*j < 65536
        float2 step = twid(NHALF, 8 * n2);
        #pragma unroll
        for (int m = 0; m < 8; m++) {
            int k1 = j + 8*m;
            zs[k1 * N2 + n2] = cmul(v[m], acc);
            acc = cmul(acc, step);
        }
    }
}

// ---------------------------------------------------------------------------
// Stage 2: per paired rows {g, 64-g} ({0,32} for g==0):
//   fwd FFT-2048 (radix 8,8,8,4; digit-reversed positions)
//   -> Hermitian pointwise (position-local complement p <-> 2047-p)
//   -> inverse FFT-2048 -> conj inter-twiddle W_N^{-k1*n2}, stored in place.
// ---------------------------------------------------------------------------
__global__ void __launch_bounds__(512) k_stage2() {
    __shared__ float2 smAB[2 * 2304];
    const int s = blockIdx.y;
    const int g = blockIdx.x;                   // 0..31
    const int rowA = g;
    const int rowB = (g == 0) ? 32 : 64 - g;
    const int tid = threadIdx.x;
    const int r = tid >> 8;                     // which row this thread serves
    const int u = tid & 255;
    const int myrow = r ? rowB : rowA;
    float2* zs   = g_z + (size_t)s * NN;
    float2* glob = zs + myrow * N2;
    float2* sm   = smAB + r * 2304;
    float2* smA  = smAB;
    float2* smB  = smAB + 2304;

    float2 v[8];
    // S1: radix-8 over b (stride 256), twiddle W_2048^{a*j}
    #pragma unroll
    for (int b = 0; b < 8; b++) v[b] = glob[u + 256*b];
    fft8<false>(v);
    { float2 w = twid(1024, u), acc = w;
      #pragma unroll
      for (int j = 1; j < 8; j++) { v[j] = cmul(v[j], acc); acc = cmul(acc, w); } }
    #pragma unroll
    for (int j = 0; j < 8; j++) sm[PAD(j*256 + u)] = v[j];
    __syncthreads();

    // S2: radix-8 over d (stride 32), twiddle W_256^{c*j2}
    { const int j = u >> 5, c = u & 31, base = j*256 + c;
      #pragma unroll
      for (int d = 0; d < 8; d++) v[d] = sm[PAD(base + 32*d)];
      fft8<false>(v);
      float2 w = twid(128, c), acc = w;
      #pragma unroll
      for (int j2 = 1; j2 < 8; j2++) { v[j2] = cmul(v[j2], acc); acc = cmul(acc, w); }
      #pragma unroll
      for (int j2 = 0; j2 < 8; j2++) sm[PAD(j*256 + j2*32 + c)] = v[j2];
    }
    __syncthreads();

    // S3: radix-8 over f (stride 4), twiddle W_32^{e*j3}
    { const int j = u >> 5, j2 = (u >> 2) & 7, e = u & 3, base = j*256 + j2*32 + e;
      #pragma unroll
      for (int f = 0; f < 8; f++) v[f] = sm[PAD(base + 4*f)];
      fft8<false>(v);
      float2 w = twid(16, e), acc = w;
      #pragma unroll
      for (int j3 = 1; j3 < 8; j3++) { v[j3] = cmul(v[j3], acc); acc = cmul(acc, w); }
      #pragma unroll
      for (int j3 = 0; j3 < 8; j3++) sm[PAD(j*256 + j2*32 + j3*4 + e)] = v[j3];
    }
    __syncthreads();

    // S4: radix-4 over e (stride 1); 2 groups per thread per row
    #pragma unroll
    for (int gi = 0; gi < 2; gi++) {
        const int grp = u + 256*gi;
        float2 w4[4];
        #pragma unroll
        for (int e = 0; e < 4; e++) w4[e] = sm[PAD(4*grp + e)];
        fft4<false>(w4);
        #pragma unroll
        for (int m = 0; m < 4; m++) sm[PAD(4*grp + m)] = w4[m];
    }
    __syncthreads();

    if (g != 0) {
        // pointwise fused with inverse radix-4 (IS4); thread tid owns
        // A-group tid and B-group 511-tid — no cross-thread hazards.
        float2 ya[4], yb[4];
        #pragma unroll
        for (int e = 0; e < 4; e++) {
            float2 Za = smA[PAD(4*tid + e)];
            float2 Zb = smB[PAD(2047 - 4*tid - e)];
            float2 Y = pw(Za, Zb);
            ya[e]   = Y;
            yb[3-e] = cconj(Y);
        }
        fft4<true>(ya);
        fft4<true>(yb);
        #pragma unroll
        for (int e = 0; e < 4; e++) smA[PAD(4*tid + e)] = ya[e];
        #pragma unroll
        for (int e = 0; e < 4; e++) smB[PAD(4*(511 - tid) + e)] = yb[e];
    } else {
        // row 0 pairs with itself at k2' = (2048-k2) mod 2048 (k2-space);
        // row 32 self-pairs position-locally.
        if (tid < 256) {
            #pragma unroll
            for (int e = 0; e < 4; e++) {
                int k2 = 4*tid + e;
                int pa = POS(k2);
                int pb = POS((2048 - k2) & 2047);
                float2 Za = smA[PAD(pa)];
                float2 Zb = smA[PAD(pb)];
                float2 Y = pw(Za, Zb);
                smA[PAD(pa)] = Y;
                smA[PAD(pb)] = cconj(Y);
            }
            if (tid == 0) {                      // k2 = 1024 self-pair, pos = 2
                float2 Za = smA[PAD(2)];
                smA[PAD(2)] = pw(Za, Za);
            }
        } else {
            const int u2 = tid - 256;
            #pragma unroll
            for (int e = 0; e < 4; e++) {
                int p = 4*u2 + e;
                float2 Za = smB[PAD(p)];
                float2 Zb = smB[PAD(2047 - p)];
                float2 Y = pw(Za, Zb);
                smB[PAD(p)]        = Y;
                smB[PAD(2047 - p)] = cconj(Y);
            }
        }
        __syncthreads();
        // IS4 separate
        #pragma unroll
        for (int gi = 0; gi < 2; gi++) {
            const int grp = u + 256*gi;
            float2 w4[4];
            #pragma unroll
            for (int e = 0; e < 4; e++) w4[e] = sm[PAD(4*grp + e)];
            fft4<true>(w4);
            #pragma unroll
            for (int e = 0; e < 4; e++) sm[PAD(4*grp + e)] = w4[e];
        }
    }
    __syncthreads();

    // IS3: conj twiddle W_32^{-e*j3}, inverse radix-8 over j3 -> f
    { const int j = u >> 5, j2 = (u >> 2) & 7, e = u & 3, base = j*256 + j2*32 + e;
      #pragma unroll
      for (int j3 = 0; j3 < 8; j3++) v[j3] = sm[PAD(base + 4*j3)];
      { float2 w = cconj(twid(16, e)), acc = w;
        #pragma unroll
        for (int j3 = 1; j3 < 8; j3++) { v[j3] = cmul(v[j3], acc); acc = cmul(acc, w); } }
      fft8<true>(v);
      #pragma unroll
      for (int f = 0; f < 8; f++) sm[PAD(base + 4*f)] = v[f];
    }
    __syncthreads();

    // IS2: conj twiddle W_256^{-c*j2}, inverse radix-8 over j2 -> d
    { const int j = u >> 5, c = u & 31, base = j*256 + c;
      #pragma unroll
      for (int j2 = 0; j2 < 8; j2++) v[j2] = sm[PAD(base + 32*j2)];
      { float2 w = cconj(twid(128, c)), acc = w;
        #pragma unroll
        for (int j2 = 1; j2 < 8; j2++) { v[j2] = cmul(v[j2], acc); acc = cmul(acc, w); } }
      fft8<true>(v);
      #pragma unroll
      for (int d = 0; d < 8; d++) sm[PAD(base + 32*d)] = v[d];
    }
    __syncthreads();

    // IS1: conj twiddle W_2048^{-a*j}, inverse radix-8 over j -> b,
    // conj inter-step twiddle W_N^{-row*(b*256+a)}, store.
    { const int a = u;
      #pragma unroll
      for (int j = 0; j < 8; j++) v[j] = sm[PAD(j*256 + a)];
      { float2 w = cconj(twid(1024, a)), acc = w;
        #pragma unroll
        for (int j = 1; j < 8; j++) { v[j] = cmul(v[j], acc); acc = cmul(acc, w); } }
      fft8<true>(v);
      float2 acc  = cconj(twid(NHALF, myrow * a));
      float2 step = cconj(twid(NHALF, 256 * myrow));
      #pragma unroll
      for (int b = 0; b < 8; b++) {
          glob[b*256 + a] = cmul(v[b], acc);
          acc = cmul(acc, step);
      }
    }
}

// ---------------------------------------------------------------------------
// Stage 3: inverse 64-pt FFT along k1 (two register radix-8 passes, one smem
// exchange), scale 1/N, write real part of n1 < 32 only.
// ---------------------------------------------------------------------------
__global__ void __launch_bounds__(256) k_stage3(float* __restrict__ out) {
    __shared__ float2 sm[64 * 32];
    const int s   = blockIdx.y;
    const int col = threadIdx.x & 31;
    const int j   = threadIdx.x >> 5;
    const int n2  = blockIdx.x * 32 + col;
    float2* zs = g_z + (size_t)s * NN;

    float2 v[8];
    #pragma unroll
    for (int m = 0; m < 8; m++) v[m] = zs[(j + 8*m) * N2 + n2];
    fft8<true>(v);                               // over m -> a
    #pragma unroll
    for (int a = 0; a < 8; a++) sm[(a*8 + j)*32 + col] = v[a];
    __syncthreads();

    const int a = threadIdx.x >> 5;
    #pragma unroll
    for (int q = 0; q < 8; q++) v[q] = sm[(a*8 + q)*32 + col];
    { float2 w = cconj(twid(32, a)), acc = w;
      #pragma unroll
      for (int q = 1; q < 8; q++) { v[q] = cmul(v[q], acc); acc = cmul(acc, w); } }
    fft8<true>(v);                               // over j -> b ; n1 = a + 8b

    const float sc = 1.0f / (float)NN;
    float* os = out + (size_t)s * T_LEN;
    #pragma unroll
    for (int b = 0; b < 4; b++)
        os[(a + 8*b) * N2 + n2] = v[b].x * sc;
}

extern "C" void kernel_launch(void* const* d_in, const int* in_sizes, int n_in,
                              void* d_out, int out_size) {
    const float* x = (const float*)d_in[0];
    const float* h = (const float*)d_in[1];
    float* out = (float*)d_out;

    k_init_tw<<<NN / 256, 256>>>();
    k_stage1<<<dim3(N2 / 32, SEQ), 256>>>(x, h);
    k_stage2<<<dim3(32, SEQ), 512>>>();
    k_stage3<<<dim3(N2 / 32, SEQ), 256>>>(out);
}

// round 4
// speedup vs baseline: 3.6597x; 1.1999x over previous
#include <cuda_runtime.h>
#include <cuda_bf16.h>

#define SEQ   512
#define T_LEN 65536
#define NN    131072
#define NHALF 65536
#define N2    2048

// Scratch (device globals; no allocations allowed)
__device__ float2 g_z[(size_t)SEQ * NN];   // 512 MiB workspace
__device__ float2 g_tw[NN];                // g_tw[h+p] = exp(-i*pi*p/h)

static __device__ __forceinline__ float2 cmul(float2 a, float2 b) {
    return make_float2(fmaf(a.x, b.x, -a.y * b.y), fmaf(a.x, b.y, a.y * b.x));
}
static __device__ __forceinline__ float2 cadd(float2 a, float2 b) { return make_float2(a.x+b.x, a.y+b.y); }
static __device__ __forceinline__ float2 csub(float2 a, float2 b) { return make_float2(a.x-b.x, a.y-b.y); }
static __device__ __forceinline__ float2 mulnI(float2 a) { return make_float2(a.y, -a.x); }   // * (-i)
static __device__ __forceinline__ float2 mulpI(float2 a) { return make_float2(-a.y, a.x); }   // * (+i)
static __device__ __forceinline__ float2 cconj(float2 a) { return make_float2(a.x, -a.y); }

// W_{2*Mhalf}^q  for q in [0, 2*Mhalf)
static __device__ __forceinline__ float2 twid(int Mhalf, int q) {
    if (q < Mhalf) return g_tw[Mhalf + q];
    float2 t = g_tw[q];                    // == g_tw[Mhalf + (q - Mhalf)]
    return make_float2(-t.x, -t.y);
}

// 8-pt DFT, natural in/out. INV => conjugated twiddles (unnormalized inverse).
template<bool INV>
static __device__ __forceinline__ void fft8(float2 z[8]) {
    const float C = 0.70710678118654752440f;
    float2 t0=cadd(z[0],z[4]), t1=cadd(z[1],z[5]), t2=cadd(z[2],z[6]), t3=cadd(z[3],z[7]);
    float2 s0=csub(z[0],z[4]), s1=csub(z[1],z[5]), s2=csub(z[2],z[6]), s3=csub(z[3],z[7]);
    if (!INV) {
        s1 = cmul(s1, make_float2(C,-C)); s2 = mulnI(s2); s3 = cmul(s3, make_float2(-C,-C));
    } else {
        s1 = cmul(s1, make_float2(C, C)); s2 = mulpI(s2); s3 = cmul(s3, make_float2(-C, C));
    }
    float2 a0=cadd(t0,t2), a1=csub(t0,t2), a2=cadd(t1,t3), a3=csub(t1,t3);
    a3 = INV ? mulpI(a3) : mulnI(a3);
    float2 b0=cadd(s0,s2), b1=csub(s0,s2), b2=cadd(s1,s3), b3=csub(s1,s3);
    b3 = INV ? mulpI(b3) : mulnI(b3);
    z[0]=cadd(a0,a2); z[4]=csub(a0,a2);
    z[2]=cadd(a1,a3); z[6]=csub(a1,a3);
    z[1]=cadd(b0,b2); z[5]=csub(b0,b2);
    z[3]=cadd(b1,b3); z[7]=csub(b1,b3);
}

template<bool INV>
static __device__ __forceinline__ void fft4(float2 z[4]) {
    float2 a0=cadd(z[0],z[2]), a1=csub(z[0],z[2]);
    float2 a2=cadd(z[1],z[3]), a3=csub(z[1],z[3]);
    a3 = INV ? mulpI(a3) : mulnI(a3);
    z[0]=cadd(a0,a2); z[2]=csub(a0,a2);
    z[1]=cadd(a1,a3); z[3]=csub(a1,a3);
}

// Hermitian unpack + pointwise: Za = Z[k], Zb = Z[N-k]; returns Y[k] = X[k]*H[k]
static __device__ __forceinline__ float2 pw(float2 Za, float2 Zb) {
    float2 X = make_float2(0.5f*(Za.x+Zb.x),  0.5f*(Za.y-Zb.y));
    float2 H = make_float2(0.5f*(Za.y+Zb.y), -0.5f*(Za.x-Zb.x));
    return cmul(X, H);
}

#define PAD(p) ((p) + (((p) >> 5) << 2))
#define POS(k2) ((((k2)&7)<<8) + ((((k2)>>3)&7)<<5) + ((((k2)>>6)&7)<<2) + ((k2)>>9))

__global__ void k_init_tw() {
    int idx = blockIdx.x * blockDim.x + threadIdx.x;
    if (idx >= NN) return;
    if (idx == 0) { g_tw[0] = make_float2(1.0f, 0.0f); return; }
    int h = 1 << (31 - __clz(idx));
    int p = idx - h;
    double ang = -3.14159265358979323846 * (double)p / (double)h;
    double s, c;
    sincos(ang, &s, &c);
    g_tw[idx] = make_float2((float)c, (float)s);
}

// ---------------------------------------------------------------------------
// Stage 1: pack z = bf16(x) + i*h (rows n1>=32 are zero) + 64-pt FFT along n1
// (two register radix-8 passes, one smem exchange) + twiddle W_N^{k1*n2}.
// Output: g_z[s][k1*2048 + n2]
// ---------------------------------------------------------------------------
__global__ void __launch_bounds__(256) k_stage1(const float* __restrict__ x,
                                                const float* __restrict__ hk) {
    __shared__ float2 sm[64 * 32];
    const int s   = blockIdx.y;
    const int col = threadIdx.x & 31;
    const int a   = threadIdx.x >> 5;          // 0..7
    const int n2  = blockIdx.x * 32 + col;
    const float* xs = x  + (size_t)s * T_LEN;
    const float* hs = hk + (size_t)s * T_LEN;

    float2 v[8];
    #pragma unroll
    for (int b = 0; b < 4; b++) {
        int n = (a + 8*b) * N2 + n2;           // < 65536 always
        v[b] = make_float2(__bfloat162float(__float2bfloat16_rn(xs[n])), hs[n]);
    }
    // fft8 over b with upper half zero (t = z, s = z)
    {
        const float C = 0.70710678118654752440f;
        float2 t0=v[0], t1=v[1], t2=v[2], t3=v[3];
        float2 s0=v[0];
        float2 s1=cmul(v[1], make_float2(C,-C));
        float2 s2=mulnI(v[2]);
        float2 s3=cmul(v[3], make_float2(-C,-C));
        float2 a0=cadd(t0,t2), a1=csub(t0,t2), a2=cadd(t1,t3), a3=mulnI(csub(t1,t3));
        float2 b0=cadd(s0,s2), b1=csub(s0,s2), b2=cadd(s1,s3), b3=mulnI(csub(s1,s3));
        v[0]=cadd(a0,a2); v[4]=csub(a0,a2);
        v[2]=cadd(a1,a3); v[6]=csub(a1,a3);
        v[1]=cadd(b0,b2); v[5]=csub(b0,b2);
        v[3]=cadd(b1,b3); v[7]=csub(b1,b3);
    }
    // twiddle W_64^{a*j}
    {
        float2 w = twid(32, a), acc = w;
        #pragma unroll
        for (int j = 1; j < 8; j++) { v[j] = cmul(v[j], acc); acc = cmul(acc, w); }
    }
    #pragma unroll
    for (int j = 0; j < 8; j++) sm[(j*8 + a)*32 + col] = v[j];
    __syncthreads();

    const int j = a;                            // phase-2 role
    #pragma unroll
    for (int q = 0; q < 8; q++) v[q] = sm[(j*8 + q)*32 + col];
    fft8<false>(v);                             // over a -> m ; k1 = j + 8m

    float2* zs = g_z + (size_t)s * NN;
    {
        float2 acc  = twid(NHALF, n2 * j);      // n2*j < 65536
        float2 step = twid(NHALF, 8 * n2);
        #pragma unroll
        for (int m = 0; m < 8; m++) {
            int k1 = j + 8*m;
            zs[k1 * N2 + n2] = cmul(v[m], acc);
            acc = cmul(acc, step);
        }
    }
}

// ---------------------------------------------------------------------------
// Stage 2: per paired rows {g, 64-g} ({0,32} for g==0):
//   fwd FFT-2048 both rows (radix 8,8,8,4; digit-reversed positions)
//   -> Hermitian pointwise (complement p <-> 2047-p is position-local)
//   -> inverse FFT-2048 for row A ONLY (output realness implies
//      u[64-k1] = conj(u[k1]) after the conj inter-twiddle, so rows > 32
//      are never materialized) -> store rows 0..32 only.
// ---------------------------------------------------------------------------
__global__ void __launch_bounds__(512) k_stage2() {
    __shared__ float2 smAB[2 * 2304];
    const int s = blockIdx.y;
    const int g = blockIdx.x;                   // 0..31
    const int rowA = g;
    const int rowB = (g == 0) ? 32 : 64 - g;
    const int tid = threadIdx.x;
    const int r = tid >> 8;                     // which row this thread serves
    const int u = tid & 255;
    const int myrow = r ? rowB : rowA;
    const bool invB = (g == 0);                 // does row B need the inverse path?
    float2* zs   = g_z + (size_t)s * NN;
    float2* glob = zs + myrow * N2;
    float2* sm   = smAB + r * 2304;
    float2* smA  = smAB;
    float2* smB  = smAB + 2304;

    float2 v[8];
    // S1: radix-8 over b (stride 256), twiddle W_2048^{a*j}
    #pragma unroll
    for (int b = 0; b < 8; b++) v[b] = glob[u + 256*b];
    fft8<false>(v);
    { float2 w = twid(1024, u), acc = w;
      #pragma unroll
      for (int j = 1; j < 8; j++) { v[j] = cmul(v[j], acc); acc = cmul(acc, w); } }
    #pragma unroll
    for (int j = 0; j < 8; j++) sm[PAD(j*256 + u)] = v[j];
    __syncthreads();

    // S2: radix-8 over d (stride 32), twiddle W_256^{c*j2}
    { const int j = u >> 5, c = u & 31, base = j*256 + c;
      #pragma unroll
      for (int d = 0; d < 8; d++) v[d] = sm[PAD(base + 32*d)];
      fft8<false>(v);
      float2 w = twid(128, c), acc = w;
      #pragma unroll
      for (int j2 = 1; j2 < 8; j2++) { v[j2] = cmul(v[j2], acc); acc = cmul(acc, w); }
      #pragma unroll
      for (int j2 = 0; j2 < 8; j2++) sm[PAD(j*256 + j2*32 + c)] = v[j2];
    }
    __syncthreads();

    // S3: radix-8 over f (stride 4), twiddle W_32^{e*j3}
    { const int j = u >> 5, j2 = (u >> 2) & 7, e = u & 3, base = j*256 + j2*32 + e;
      #pragma unroll
      for (int f = 0; f < 8; f++) v[f] = sm[PAD(base + 4*f)];
      fft8<false>(v);
      float2 w = twid(16, e), acc = w;
      #pragma unroll
      for (int j3 = 1; j3 < 8; j3++) { v[j3] = cmul(v[j3], acc); acc = cmul(acc, w); }
      #pragma unroll
      for (int j3 = 0; j3 < 8; j3++) sm[PAD(j*256 + j2*32 + j3*4 + e)] = v[j3];
    }
    __syncthreads();

    // S4: radix-4 over e (stride 1); 2 groups per thread per row
    #pragma unroll
    for (int gi = 0; gi < 2; gi++) {
        const int grp = u + 256*gi;
        float2 w4[4];
        #pragma unroll
        for (int e = 0; e < 4; e++) w4[e] = sm[PAD(4*grp + e)];
        fft4<false>(w4);
        #pragma unroll
        for (int m = 0; m < 4; m++) sm[PAD(4*grp + m)] = w4[m];
    }
    __syncthreads();

    if (g != 0) {
        // pointwise fused with inverse radix-4, ROW A ONLY; all 512 threads
        // (thread t owns A-group t; smB is read-only from here on).
        float2 ya[4];
        #pragma unroll
        for (int e = 0; e < 4; e++) {
            float2 Za = smA[PAD(4*tid + e)];
            float2 Zb = smB[PAD(2047 - 4*tid - e)];
            ya[e] = pw(Za, Zb);
        }
        fft4<true>(ya);
        #pragma unroll
        for (int e = 0; e < 4; e++) smA[PAD(4*tid + e)] = ya[e];
    } else {
        // row 0 pairs with itself at k2' = (2048-k2) mod 2048 (k2-space);
        // row 32 self-pairs position-locally. Both rows stay (both <= 32).
        if (tid < 256) {
            #pragma unroll
            for (int e = 0; e < 4; e++) {
                int k2 = 4*tid + e;
                int pa = POS(k2);
                int pb = POS((2048 - k2) & 2047);
                float2 Za = smA[PAD(pa)];
                float2 Zb = smA[PAD(pb)];
                float2 Y = pw(Za, Zb);
                smA[PAD(pa)] = Y;
                smA[PAD(pb)] = cconj(Y);
            }
            if (tid == 0) {                      // k2 = 1024 self-pair, pos = 2
                float2 Za = smA[PAD(2)];
                smA[PAD(2)] = pw(Za, Za);
            }
        } else {
            const int u2 = tid - 256;
            #pragma unroll
            for (int e = 0; e < 4; e++) {
                int p = 4*u2 + e;
                float2 Za = smB[PAD(p)];
                float2 Zb = smB[PAD(2047 - p)];
                float2 Y = pw(Za, Zb);
                smB[PAD(p)]        = Y;
                smB[PAD(2047 - p)] = cconj(Y);
            }
        }
        __syncthreads();
        // IS4 separate (both rows)
        #pragma unroll
        for (int gi = 0; gi < 2; gi++) {
            const int grp = u + 256*gi;
            float2 w4[4];
            #pragma unroll
            for (int e = 0; e < 4; e++) w4[e] = sm[PAD(4*grp + e)];
            fft4<true>(w4);
            #pragma unroll
            for (int e = 0; e < 4; e++) sm[PAD(4*grp + e)] = w4[e];
        }
    }
    __syncthreads();

    // IS3: conj twiddle W_32^{-e*j3}, inverse radix-8 over j3 -> f
    if (r == 0 || invB) {
      const int j = u >> 5, j2 = (u >> 2) & 7, e = u & 3, base = j*256 + j2*32 + e;
      #pragma unroll
      for (int j3 = 0; j3 < 8; j3++) v[j3] = sm[PAD(base + 4*j3)];
      { float2 w = cconj(twid(16, e)), acc = w;
        #pragma unroll
        for (int j3 = 1; j3 < 8; j3++) { v[j3] = cmul(v[j3], acc); acc = cmul(acc, w); } }
      fft8<true>(v);
      #pragma unroll
      for (int f = 0; f < 8; f++) sm[PAD(base + 4*f)] = v[f];
    }
    __syncthreads();

    // IS2: conj twiddle W_256^{-c*j2}, inverse radix-8 over j2 -> d
    if (r == 0 || invB) {
      const int j = u >> 5, c = u & 31, base = j*256 + c;
      #pragma unroll
      for (int j2 = 0; j2 < 8; j2++) v[j2] = sm[PAD(base + 32*j2)];
      { float2 w = cconj(twid(128, c)), acc = w;
        #pragma unroll
        for (int j2 = 1; j2 < 8; j2++) { v[j2] = cmul(v[j2], acc); acc = cmul(acc, w); } }
      fft8<true>(v);
      #pragma unroll
      for (int d = 0; d < 8; d++) sm[PAD(base + 32*d)] = v[d];
    }
    __syncthreads();

    // IS1: conj twiddle W_2048^{-a*j}, inverse radix-8 over j -> b,
    // conj inter-step twiddle W_N^{-row*(b*256+a)}, store (rows <= 32 only).
    if (r == 0 || invB) {
      const int a = u;
      #pragma unroll
      for (int j = 0; j < 8; j++) v[j] = sm[PAD(j*256 + a)];
      { float2 w = cconj(twid(1024, a)), acc = w;
        #pragma unroll
        for (int j = 1; j < 8; j++) { v[j] = cmul(v[j], acc); acc = cmul(acc, w); } }
      fft8<true>(v);
      float2 acc  = cconj(twid(NHALF, myrow * a));
      float2 step = cconj(twid(NHALF, 256 * myrow));
      #pragma unroll
      for (int b = 0; b < 8; b++) {
          glob[b*256 + a] = cmul(v[b], acc);
          acc = cmul(acc, step);
      }
    }
}

// ---------------------------------------------------------------------------
// Stage 3: inverse 64-pt FFT along k1 (two register radix-8 passes, one smem
// exchange), scale 1/N, write real part of n1 < 32 only. Rows 33..63 are
// reconstructed as conj(row 64-r) — never read from DRAM.
// ---------------------------------------------------------------------------
__global__ void __launch_bounds__(256) k_stage3(float* __restrict__ out) {
    __shared__ float2 sm[64 * 32];
    const int s   = blockIdx.y;
    const int col = threadIdx.x & 31;
    const int j   = threadIdx.x >> 5;
    const int n2  = blockIdx.x * 32 + col;
    float2* zs = g_z + (size_t)s * NN;

    float2 v[8];
    #pragma unroll
    for (int m = 0; m < 8; m++) {
        int rr = j + 8*m;
        if (rr <= 32) {
            v[m] = zs[rr * N2 + n2];
        } else {
            v[m] = cconj(zs[(64 - rr) * N2 + n2]);
        }
    }
    fft8<true>(v);                               // over m -> a
    #pragma unroll
    for (int a = 0; a < 8; a++) sm[(a*8 + j)*32 + col] = v[a];
    __syncthreads();

    const int a = threadIdx.x >> 5;
    #pragma unroll
    for (int q = 0; q < 8; q++) v[q] = sm[(a*8 + q)*32 + col];
    { float2 w = cconj(twid(32, a)), acc = w;
      #pragma unroll
      for (int q = 1; q < 8; q++) { v[q] = cmul(v[q], acc); acc = cmul(acc, w); } }
    fft8<true>(v);                               // over j -> b ; n1 = a + 8b

    const float sc = 1.0f / (float)NN;
    float* os = out + (size_t)s * T_LEN;
    #pragma unroll
    for (int b = 0; b < 4; b++)
        os[(a + 8*b) * N2 + n2] = v[b].x * sc;
}

extern "C" void kernel_launch(void* const* d_in, const int* in_sizes, int n_in,
                              void* d_out, int out_size) {
    const float* x = (const float*)d_in[0];
    const float* h = (const float*)d_in[1];
    float* out = (float*)d_out;

    k_init_tw<<<NN / 256, 256>>>();
    k_stage1<<<dim3(N2 / 32, SEQ), 256>>>(x, h);
    k_stage2<<<dim3(32, SEQ), 512>>>();
    k_stage3<<<dim3(N2 / 32, SEQ), 256>>>(out);
}